// round 1
// baseline (speedup 1.0000x reference)
#include <cuda_runtime.h>
#include <math.h>

// Problem dims (fixed by reference)
#define BB     8192
#define MM     200
#define EE     64      // E
#define NOTHER 128
#define H1     96      // ADIM/2
#define F1     128     // FEA/2
#define F2     85      // FEA/3
#define F3     64      // FEA/4

__global__ __launch_bounds__(256, 2)
void din_kernel(const float* __restrict__ hist,   // (B, M, E)
                const float* __restrict__ target, // (B, E)
                const float* __restrict__ other,  // (B, 128)
                const float* __restrict__ aW1,    // (192, 96)
                const float* __restrict__ ab1,    // (96)
                const float* __restrict__ aW2,    // (96, 1)
                const float* __restrict__ ab2,    // (1)
                const float* __restrict__ oW1,    // (256, 128)
                const float* __restrict__ ob1,    // (128)
                const float* __restrict__ oW2,    // (128, 85)
                const float* __restrict__ ob2,    // (85)
                const float* __restrict__ oW3,    // (85, 64)
                const float* __restrict__ ob3,    // (64)
                const float* __restrict__ fW,     // (64, 1)
                const float* __restrict__ fb,     // (1)
                float* __restrict__ out)          // (B, 1)
{
    __shared__ float s_tgt[EE];
    __shared__ float s_W[EE * H1];   // W1eff = W1a + diag(tgt)*W1b   (24 KB)
    __shared__ float s_c[H1];        // ab1 + tgt @ W1c
    __shared__ float s_w2[H1];
    __shared__ float s_aij[256];
    __shared__ float s_part[4 * EE];
    __shared__ float s_x[256];
    __shared__ float s_h1[F1];
    __shared__ float s_h2[F2 + 3];
    __shared__ float s_h3[F3];

    const int b = blockIdx.x;
    const int t = threadIdx.x;
    const float* hb = hist + (size_t)b * MM * EE;

    if (t < EE) s_tgt[t] = target[(size_t)b * EE + t];
    if (t < H1) s_w2[t]  = aW2[t];
    __syncthreads();

    // ---- Build W1eff in smem + constant vector c ----
    for (int idx = t; idx < EE * H1; idx += 256) {
        int e = idx / H1;
        s_W[idx] = aW1[idx] + s_tgt[e] * aW1[EE * H1 + idx];
    }
    if (t < H1) {
        float acc = ab1[t];
        #pragma unroll 8
        for (int e = 0; e < EE; e++)
            acc = fmaf(s_tgt[e], aW1[(2 * EE + e) * H1 + t], acc);
        s_c[t] = acc;
    }
    __syncthreads();

    // ---- Attention scores: one hist row per thread (t < 200) ----
    float aij = 0.f;
    if (t < MM) {
        float r[EE];
        const float4* hr = (const float4*)(hb + (size_t)t * EE);
        #pragma unroll
        for (int i = 0; i < EE / 4; i++) {
            float4 v = hr[i];
            r[4*i+0] = v.x; r[4*i+1] = v.y; r[4*i+2] = v.z; r[4*i+3] = v.w;
        }
        aij = ab2[0];
        #pragma unroll 1
        for (int j0 = 0; j0 < H1; j0 += 4) {
            float4 acc = *(const float4*)&s_c[j0];
            #pragma unroll
            for (int e = 0; e < EE; e++) {
                float4 w = *(const float4*)&s_W[e * H1 + j0];   // uniform addr -> broadcast
                acc.x = fmaf(r[e], w.x, acc.x);
                acc.y = fmaf(r[e], w.y, acc.y);
                acc.z = fmaf(r[e], w.z, acc.z);
                acc.w = fmaf(r[e], w.w, acc.w);
            }
            float4 w2 = *(const float4*)&s_w2[j0];
            aij = fmaf(fmaxf(acc.x, 0.f), w2.x, aij);
            aij = fmaf(fmaxf(acc.y, 0.f), w2.y, aij);
            aij = fmaf(fmaxf(acc.z, 0.f), w2.z, aij);
            aij = fmaf(fmaxf(acc.w, 0.f), w2.w, aij);
        }
    }
    s_aij[t] = (t < MM) ? aij : 0.f;
    __syncthreads();

    // ---- tmp[e] = sum_m aij[m] * hist[m][e]  (4-way m-split, coalesced) ----
    {
        const int chunk = t >> 6;        // 0..3, 50 m-rows each
        const int e     = t & 63;
        float acc = 0.f;
        const int m0 = chunk * 50;
        #pragma unroll 5
        for (int m = m0; m < m0 + 50; m++)
            acc = fmaf(s_aij[m], hb[(size_t)m * EE + e], acc);
        s_part[chunk * EE + e] = acc;
    }
    __syncthreads();

    // ---- x = concat(tmp, target, other) ----
    if (t < EE) {
        s_x[t]      = s_part[t] + s_part[EE + t] + s_part[2 * EE + t] + s_part[3 * EE + t];
        s_x[EE + t] = s_tgt[t];
    }
    if (t < NOTHER) s_x[2 * EE + t] = other[(size_t)b * NOTHER + t];
    __syncthreads();

    // ---- MLP head ----
    if (t < F1) {
        float acc = ob1[t];
        #pragma unroll 8
        for (int k = 0; k < 256; k++)
            acc = fmaf(s_x[k], oW1[k * F1 + t], acc);
        s_h1[t] = fmaxf(acc, 0.f);
    }
    __syncthreads();
    if (t < F2) {
        float acc = ob2[t];
        #pragma unroll 8
        for (int k = 0; k < F1; k++)
            acc = fmaf(s_h1[k], oW2[k * F2 + t], acc);
        s_h2[t] = fmaxf(acc, 0.f);
    }
    __syncthreads();
    if (t < F3) {
        float acc = ob3[t];
        #pragma unroll 5
        for (int k = 0; k < F2; k++)
            acc = fmaf(s_h2[k], oW3[k * F3 + t], acc);
        s_h3[t] = fmaxf(acc, 0.f);
    }
    __syncthreads();
    if (t < 32) {
        float v = s_h3[t] * fW[t] + s_h3[t + 32] * fW[t + 32];
        #pragma unroll
        for (int off = 16; off; off >>= 1)
            v += __shfl_xor_sync(0xffffffffu, v, off);
        if (t == 0)
            out[b] = 1.f / (1.f + expf(-(v + fb[0])));
    }
}

extern "C" void kernel_launch(void* const* d_in, const int* in_sizes, int n_in,
                              void* d_out, int out_size)
{
    const float* hist   = (const float*)d_in[0];
    const float* target = (const float*)d_in[1];
    const float* other  = (const float*)d_in[2];
    const float* aW1    = (const float*)d_in[3];
    const float* ab1    = (const float*)d_in[4];
    const float* aW2    = (const float*)d_in[5];
    const float* ab2    = (const float*)d_in[6];
    const float* oW1    = (const float*)d_in[7];
    const float* ob1    = (const float*)d_in[8];
    const float* oW2    = (const float*)d_in[9];
    const float* ob2    = (const float*)d_in[10];
    const float* oW3    = (const float*)d_in[11];
    const float* ob3    = (const float*)d_in[12];
    const float* fW     = (const float*)d_in[13];
    const float* fb     = (const float*)d_in[14];
    float* out = (float*)d_out;

    din_kernel<<<BB, 256>>>(hist, target, other, aW1, ab1, aW2, ab2,
                            oW1, ob1, oW2, ob2, oW3, ob3, fW, fb, out);
}

// round 2
// speedup vs baseline: 2.3777x; 2.3777x over previous
#include <cuda_runtime.h>
#include <math.h>

// Problem dims (fixed by reference)
#define BB     8192
#define MM     200
#define EE     64      // E (= K of attention GEMM)
#define NOTHER 128
#define H1     96      // ADIM/2 (= N of attention GEMM)
#define WP     104     // padded smem stride for W1eff (conflict-free B frags)
#define F1     128     // FEA/2
#define F2     85      // FEA/3
#define F3     64      // FEA/4

__device__ __forceinline__ unsigned f2tf32(float f) {
    unsigned r;
    asm("cvt.rna.tf32.f32 %0, %1;" : "=r"(r) : "f"(f));
    return r;
}

__global__ __launch_bounds__(256, 4)
void din_kernel(const float* __restrict__ hist,   // (B, M, E)
                const float* __restrict__ target, // (B, E)
                const float* __restrict__ other,  // (B, 128)
                const float* __restrict__ aW1,    // (192, 96)
                const float* __restrict__ ab1,    // (96)
                const float* __restrict__ aW2,    // (96, 1)
                const float* __restrict__ ab2,    // (1)
                const float* __restrict__ oW1,    // (256, 128)
                const float* __restrict__ ob1,    // (128)
                const float* __restrict__ oW2,    // (128, 85)
                const float* __restrict__ ob2,    // (85)
                const float* __restrict__ oW3,    // (85, 64)
                const float* __restrict__ ob3,    // (64)
                const float* __restrict__ fW,     // (64, 1)
                const float* __restrict__ fb,     // (1)
                float* __restrict__ out)          // (B, 1)
{
    __shared__ unsigned s_W[EE * WP];   // W1eff as tf32 bits, [k][n], stride 104 (~26.6 KB)
    __shared__ float s_tgt[EE];
    __shared__ float s_c[H1];           // ab1 + tgt @ W1c
    __shared__ float s_w2[H1];
    __shared__ float s_aij[208];
    __shared__ float s_part[4 * EE];
    __shared__ float s_x[256];
    __shared__ float s_h1[F1];
    __shared__ float s_h2[F2 + 3];
    __shared__ float s_h3[F3];

    const int b = blockIdx.x;
    const int t = threadIdx.x;
    const float* hb = hist + (size_t)b * MM * EE;

    if (t < EE) s_tgt[t] = target[(size_t)b * EE + t];
    if (t < H1) s_w2[t]  = aW2[t];
    __syncthreads();

    // ---- Build W1eff (= W1a + diag(tgt)·W1b) in smem as tf32 bits; c = ab1 + tgt@W1c ----
    for (int idx = t; idx < EE * H1; idx += 256) {
        int e = idx / H1;
        int j = idx - e * H1;
        float v = aW1[idx] + s_tgt[e] * aW1[EE * H1 + idx];
        s_W[e * WP + j] = f2tf32(v);
    }
    if (t < H1) {
        float acc = ab1[t];
        #pragma unroll 8
        for (int e = 0; e < EE; e++)
            acc = fmaf(s_tgt[e], aW1[(2 * EE + e) * H1 + t], acc);
        s_c[t] = acc;
    }
    __syncthreads();

    // ---- Phase 1: attention scores via tf32 mma.sync, one 16-row m-tile per warp ----
    const int warp = t >> 5;
    const int lane = t & 31;
    const int gid  = lane >> 2;   // 0..7
    const int tig  = lane & 3;    // 0..3
    const float bias2 = ab2[0];

    for (int mt = warp; mt < 13; mt += 8) {
        const int r0 = mt * 16 + gid;
        const int r1 = r0 + 8;
        const bool v0 = (r0 < MM);
        const bool v1 = (r1 < MM);

        // Hoist A fragments for all 8 k-steps (rows r0/r1, cols tig / tig+4 per step)
        unsigned a[8][4];
        const float* base0 = hb + (size_t)r0 * EE + tig;
        const float* base1 = hb + (size_t)r1 * EE + tig;
        #pragma unroll
        for (int ks = 0; ks < 8; ks++) {
            const int k0 = ks * 8;
            float x0 = v0 ? base0[k0]     : 0.f;
            float x1 = v1 ? base1[k0]     : 0.f;
            float x2 = v0 ? base0[k0 + 4] : 0.f;
            float x3 = v1 ? base1[k0 + 4] : 0.f;
            a[ks][0] = f2tf32(x0);
            a[ks][1] = f2tf32(x1);
            a[ks][2] = f2tf32(x2);
            a[ks][3] = f2tf32(x3);
        }

        float aij0 = 0.f, aij1 = 0.f;
        const unsigned* wbase = s_W + tig * WP + gid;   // + ks*8*WP + n0

        #pragma unroll 1
        for (int nt = 0; nt < 12; nt++) {
            const int n0 = nt * 8;
            float c0 = 0.f, c1 = 0.f, c2 = 0.f, c3 = 0.f;
            #pragma unroll
            for (int ks = 0; ks < 8; ks++) {
                unsigned b0 = wbase[ks * 8 * WP + n0];            // B[k=8ks+tig  ][n0+gid]
                unsigned b1 = wbase[(ks * 8 + 4) * WP + n0];      // B[k=8ks+tig+4][n0+gid]
                asm volatile(
                    "mma.sync.aligned.m16n8k8.row.col.f32.tf32.tf32.f32 "
                    "{%0,%1,%2,%3}, {%4,%5,%6,%7}, {%8,%9}, {%0,%1,%2,%3};"
                    : "+f"(c0), "+f"(c1), "+f"(c2), "+f"(c3)
                    : "r"(a[ks][0]), "r"(a[ks][1]), "r"(a[ks][2]), "r"(a[ks][3]),
                      "r"(b0), "r"(b1));
            }
            // epilogue: h = relu(c + cvec), fold aW2 dot
            const int j0 = n0 + 2 * tig;
            const float cc0 = s_c[j0],  cc1 = s_c[j0 + 1];
            const float w0  = s_w2[j0], w1  = s_w2[j0 + 1];
            aij0 = fmaf(fmaxf(c0 + cc0, 0.f), w0, aij0);
            aij0 = fmaf(fmaxf(c1 + cc1, 0.f), w1, aij0);
            aij1 = fmaf(fmaxf(c2 + cc0, 0.f), w0, aij1);
            aij1 = fmaf(fmaxf(c3 + cc1, 0.f), w1, aij1);
        }
        // reduce across the 4 lanes of each quad (they hold different n columns)
        aij0 += __shfl_xor_sync(0xffffffffu, aij0, 1);
        aij0 += __shfl_xor_sync(0xffffffffu, aij0, 2);
        aij1 += __shfl_xor_sync(0xffffffffu, aij1, 1);
        aij1 += __shfl_xor_sync(0xffffffffu, aij1, 2);
        if (tig == 0) {
            if (v0) s_aij[r0] = aij0 + bias2;
            if (v1) s_aij[r1] = aij1 + bias2;
        }
    }
    __syncthreads();

    // ---- Phase 2: tmp[e] = sum_m aij[m] * hist[m][e]  (4-way m-split, coalesced, L2-hot) ----
    {
        const int chunk = t >> 6;        // 0..3, 50 m-rows each
        const int e     = t & 63;
        float acc = 0.f;
        const int m0 = chunk * 50;
        #pragma unroll 5
        for (int m = m0; m < m0 + 50; m++)
            acc = fmaf(s_aij[m], hb[(size_t)m * EE + e], acc);
        s_part[chunk * EE + e] = acc;
    }
    __syncthreads();

    // ---- x = concat(tmp, target, other) ----
    if (t < EE) {
        s_x[t]      = s_part[t] + s_part[EE + t] + s_part[2 * EE + t] + s_part[3 * EE + t];
        s_x[EE + t] = s_tgt[t];
    }
    if (t < NOTHER) s_x[2 * EE + t] = other[(size_t)b * NOTHER + t];
    __syncthreads();

    // ---- MLP head (weights L2-resident across CTAs) ----
    if (t < F1) {
        float acc = ob1[t];
        #pragma unroll 8
        for (int k = 0; k < 256; k++)
            acc = fmaf(s_x[k], oW1[k * F1 + t], acc);
        s_h1[t] = fmaxf(acc, 0.f);
    }
    __syncthreads();
    if (t < F2) {
        float acc = ob2[t];
        #pragma unroll 8
        for (int k = 0; k < F1; k++)
            acc = fmaf(s_h1[k], oW2[k * F2 + t], acc);
        s_h2[t] = fmaxf(acc, 0.f);
    }
    __syncthreads();
    if (t < F3) {
        float acc = ob3[t];
        #pragma unroll 5
        for (int k = 0; k < F2; k++)
            acc = fmaf(s_h2[k], oW3[k * F3 + t], acc);
        s_h3[t] = fmaxf(acc, 0.f);
    }
    __syncthreads();
    if (t < 32) {
        float v = s_h3[t] * fW[t] + s_h3[t + 32] * fW[t + 32];
        #pragma unroll
        for (int off = 16; off; off >>= 1)
            v += __shfl_xor_sync(0xffffffffu, v, off);
        if (t == 0)
            out[b] = 1.f / (1.f + expf(-(v + fb[0])));
    }
}

extern "C" void kernel_launch(void* const* d_in, const int* in_sizes, int n_in,
                              void* d_out, int out_size)
{
    const float* hist   = (const float*)d_in[0];
    const float* target = (const float*)d_in[1];
    const float* other  = (const float*)d_in[2];
    const float* aW1    = (const float*)d_in[3];
    const float* ab1    = (const float*)d_in[4];
    const float* aW2    = (const float*)d_in[5];
    const float* ab2    = (const float*)d_in[6];
    const float* oW1    = (const float*)d_in[7];
    const float* ob1    = (const float*)d_in[8];
    const float* oW2    = (const float*)d_in[9];
    const float* ob2    = (const float*)d_in[10];
    const float* oW3    = (const float*)d_in[11];
    const float* ob3    = (const float*)d_in[12];
    const float* fW     = (const float*)d_in[13];
    const float* fb     = (const float*)d_in[14];
    float* out = (float*)d_out;

    din_kernel<<<BB, 256>>>(hist, target, other, aW1, ab1, aW2, ab2,
                            oW1, ob1, oW2, ob2, oW3, ob3, fW, fb, out);
}

// round 3
// speedup vs baseline: 2.3859x; 1.0034x over previous
#include <cuda_runtime.h>
#include <math.h>

// Problem dims (fixed by reference)
#define BB     8192
#define MM     200
#define EE     64      // E (= K of attention GEMM)
#define NOTHER 128
#define H1     96      // ADIM/2 (= N of attention GEMM)
#define WP     104     // padded smem stride for W1eff (conflict-free B frags)
#define F1     128     // FEA/2
#define F2     85      // FEA/3
#define F3     64      // FEA/4

__device__ __forceinline__ unsigned f2tf32(float f) {
    unsigned r;
    asm("cvt.rna.tf32.f32 %0, %1;" : "=r"(r) : "f"(f));
    return r;
}

__global__ __launch_bounds__(256, 4)
void din_kernel(const float* __restrict__ hist,   // (B, M, E)
                const float* __restrict__ target, // (B, E)
                const float* __restrict__ other,  // (B, 128)
                const float* __restrict__ aW1,    // (192, 96)
                const float* __restrict__ ab1,    // (96)
                const float* __restrict__ aW2,    // (96, 1)
                const float* __restrict__ ab2,    // (1)
                const float* __restrict__ oW1,    // (256, 128)
                const float* __restrict__ ob1,    // (128)
                const float* __restrict__ oW2,    // (128, 85)
                const float* __restrict__ ob2,    // (85)
                const float* __restrict__ oW3,    // (85, 64)
                const float* __restrict__ ob3,    // (64)
                const float* __restrict__ fW,     // (64, 1)
                const float* __restrict__ fb,     // (1)
                float* __restrict__ out)          // (B, 1)
{
    __shared__ unsigned s_W[EE * WP];   // W1eff as tf32 bits, [k][n], stride 104 (~26.6 KB)
    __shared__ float s_tgt[EE];
    __shared__ float s_c[H1];           // ab1 + tgt @ W1c
    __shared__ float s_w2[H1];
    __shared__ float s_aij[208];
    __shared__ float s_part[4 * EE];
    __shared__ float s_x[256];
    __shared__ float s_h1[F1];
    __shared__ float s_h2[F2 + 3];
    __shared__ float s_h3[F3];

    const int b = blockIdx.x;
    const int t = threadIdx.x;
    const float* hb = hist + (size_t)b * MM * EE;

    if (t < EE) s_tgt[t] = target[(size_t)b * EE + t];
    if (t < H1) s_w2[t]  = aW2[t];
    __syncthreads();

    // ---- Build W1eff (= W1a + diag(tgt)·W1b) in smem as tf32 bits; c = ab1 + tgt@W1c ----
    for (int idx = t; idx < EE * H1; idx += 256) {
        int e = idx / H1;
        int j = idx - e * H1;
        float v = aW1[idx] + s_tgt[e] * aW1[EE * H1 + idx];
        s_W[e * WP + j] = f2tf32(v);
    }
    if (t < H1) {
        float acc = ab1[t];
        #pragma unroll 8
        for (int e = 0; e < EE; e++)
            acc = fmaf(s_tgt[e], aW1[(2 * EE + e) * H1 + t], acc);
        s_c[t] = acc;
    }
    __syncthreads();

    // ---- Phase 1: attention scores via tf32 mma.sync, one 16-row m-tile per warp ----
    const int warp = t >> 5;
    const int lane = t & 31;
    const int gid  = lane >> 2;   // 0..7
    const int tig  = lane & 3;    // 0..3
    const float bias2 = ab2[0];

    for (int mt = warp; mt < 13; mt += 8) {
        const int r0 = mt * 16 + gid;
        const int r1 = r0 + 8;
        const bool v0 = (r0 < MM);
        const bool v1 = (r1 < MM);

        // Hoist A fragments for all 8 k-steps (rows r0/r1, cols tig / tig+4 per step)
        unsigned a[8][4];
        const float* base0 = hb + (size_t)r0 * EE + tig;
        const float* base1 = hb + (size_t)r1 * EE + tig;
        #pragma unroll
        for (int ks = 0; ks < 8; ks++) {
            const int k0 = ks * 8;
            float x0 = v0 ? base0[k0]     : 0.f;
            float x1 = v1 ? base1[k0]     : 0.f;
            float x2 = v0 ? base0[k0 + 4] : 0.f;
            float x3 = v1 ? base1[k0 + 4] : 0.f;
            a[ks][0] = f2tf32(x0);
            a[ks][1] = f2tf32(x1);
            a[ks][2] = f2tf32(x2);
            a[ks][3] = f2tf32(x3);
        }

        float aij0 = 0.f, aij1 = 0.f;
        const unsigned* wbase = s_W + tig * WP + gid;   // + ks*8*WP + n0

        #pragma unroll 1
        for (int nt = 0; nt < 12; nt++) {
            const int n0 = nt * 8;
            float c0 = 0.f, c1 = 0.f, c2 = 0.f, c3 = 0.f;
            #pragma unroll
            for (int ks = 0; ks < 8; ks++) {
                unsigned b0 = wbase[ks * 8 * WP + n0];            // B[k=8ks+tig  ][n0+gid]
                unsigned b1 = wbase[(ks * 8 + 4) * WP + n0];      // B[k=8ks+tig+4][n0+gid]
                asm volatile(
                    "mma.sync.aligned.m16n8k8.row.col.f32.tf32.tf32.f32 "
                    "{%0,%1,%2,%3}, {%4,%5,%6,%7}, {%8,%9}, {%0,%1,%2,%3};"
                    : "+f"(c0), "+f"(c1), "+f"(c2), "+f"(c3)
                    : "r"(a[ks][0]), "r"(a[ks][1]), "r"(a[ks][2]), "r"(a[ks][3]),
                      "r"(b0), "r"(b1));
            }
            // epilogue: h = relu(c + cvec), fold aW2 dot
            const int j0 = n0 + 2 * tig;
            const float cc0 = s_c[j0],  cc1 = s_c[j0 + 1];
            const float w0  = s_w2[j0], w1  = s_w2[j0 + 1];
            aij0 = fmaf(fmaxf(c0 + cc0, 0.f), w0, aij0);
            aij0 = fmaf(fmaxf(c1 + cc1, 0.f), w1, aij0);
            aij1 = fmaf(fmaxf(c2 + cc0, 0.f), w0, aij1);
            aij1 = fmaf(fmaxf(c3 + cc1, 0.f), w1, aij1);
        }
        // reduce across the 4 lanes of each quad (they hold different n columns)
        aij0 += __shfl_xor_sync(0xffffffffu, aij0, 1);
        aij0 += __shfl_xor_sync(0xffffffffu, aij0, 2);
        aij1 += __shfl_xor_sync(0xffffffffu, aij1, 1);
        aij1 += __shfl_xor_sync(0xffffffffu, aij1, 2);
        if (tig == 0) {
            if (v0) s_aij[r0] = aij0 + bias2;
            if (v1) s_aij[r1] = aij1 + bias2;
        }
    }
    __syncthreads();

    // ---- Phase 2: tmp[e] = sum_m aij[m] * hist[m][e]  (4-way m-split, coalesced, L2-hot) ----
    {
        const int chunk = t >> 6;        // 0..3, 50 m-rows each
        const int e     = t & 63;
        float acc = 0.f;
        const int m0 = chunk * 50;
        #pragma unroll 5
        for (int m = m0; m < m0 + 50; m++)
            acc = fmaf(s_aij[m], hb[(size_t)m * EE + e], acc);
        s_part[chunk * EE + e] = acc;
    }
    __syncthreads();

    // ---- x = concat(tmp, target, other) ----
    if (t < EE) {
        s_x[t]      = s_part[t] + s_part[EE + t] + s_part[2 * EE + t] + s_part[3 * EE + t];
        s_x[EE + t] = s_tgt[t];
    }
    if (t < NOTHER) s_x[2 * EE + t] = other[(size_t)b * NOTHER + t];
    __syncthreads();

    // ---- MLP head (weights L2-resident across CTAs) ----
    if (t < F1) {
        float acc = ob1[t];
        #pragma unroll 8
        for (int k = 0; k < 256; k++)
            acc = fmaf(s_x[k], oW1[k * F1 + t], acc);
        s_h1[t] = fmaxf(acc, 0.f);
    }
    __syncthreads();
    if (t < F2) {
        float acc = ob2[t];
        #pragma unroll 8
        for (int k = 0; k < F1; k++)
            acc = fmaf(s_h1[k], oW2[k * F2 + t], acc);
        s_h2[t] = fmaxf(acc, 0.f);
    }
    __syncthreads();
    if (t < F3) {
        float acc = ob3[t];
        #pragma unroll 5
        for (int k = 0; k < F2; k++)
            acc = fmaf(s_h2[k], oW3[k * F3 + t], acc);
        s_h3[t] = fmaxf(acc, 0.f);
    }
    __syncthreads();
    if (t < 32) {
        float v = s_h3[t] * fW[t] + s_h3[t + 32] * fW[t + 32];
        #pragma unroll
        for (int off = 16; off; off >>= 1)
            v += __shfl_xor_sync(0xffffffffu, v, off);
        if (t == 0)
            out[b] = 1.f / (1.f + expf(-(v + fb[0])));
    }
}

extern "C" void kernel_launch(void* const* d_in, const int* in_sizes, int n_in,
                              void* d_out, int out_size)
{
    const float* hist   = (const float*)d_in[0];
    const float* target = (const float*)d_in[1];
    const float* other  = (const float*)d_in[2];
    const float* aW1    = (const float*)d_in[3];
    const float* ab1    = (const float*)d_in[4];
    const float* aW2    = (const float*)d_in[5];
    const float* ab2    = (const float*)d_in[6];
    const float* oW1    = (const float*)d_in[7];
    const float* ob1    = (const float*)d_in[8];
    const float* oW2    = (const float*)d_in[9];
    const float* ob2    = (const float*)d_in[10];
    const float* oW3    = (const float*)d_in[11];
    const float* ob3    = (const float*)d_in[12];
    const float* fW     = (const float*)d_in[13];
    const float* fb     = (const float*)d_in[14];
    float* out = (float*)d_out;

    din_kernel<<<BB, 256>>>(hist, target, other, aW1, ab1, aW2, ab2,
                            oW1, ob1, oW2, ob2, oW3, ob3, fW, fb, out);
}